// round 16
// baseline (speedup 1.0000x reference)
#include <cuda_runtime.h>
#include <cuda_bf16.h>

// FEM H8 stiffness matvec (KU = sum_e scatter(K_type(e) @ gather(U,e))).
//
// v11b: binning prelude DELETED (measured k_scatter=14.2us + histo/scan made
// the prelude ~as expensive as the divergence it fixed). Instead, all 64
// 24x24 filters (147KB) are staged in SHARED MEMORY once per persistent
// block; per-lane random types then read from smem (padded stride to spread
// bank groups) instead of causing ~26-way divergent L1 replays.
//
//   1) k_prep  : pad U [N,3] -> g_u4 [N,4] (16B rows), zero g_acc [N,4]
//   2) k_main  : persistent (148 blocks x 768 thr, 1 block/SM via 148KB
//                dynamic smem). Loads all filters to smem, then grid-stride:
//                - types/nodIdx reads fully coalesced (natural order)
//                - per-node gather = ONE LDG.128 from padded g_u4
//                - Ke rows = LDS.128 from smem (pad 580 words/filter)
//                - per-node scatter = ONE red.global.add.v4.f32 into g_acc
//   3) k_final : compact g_acc [N,4] -> out [N,3], streaming stores
//
// All launches graph-capturable; scratch in __device__ globals; no static
// state in kernel_launch (attribute set unconditionally each call).

#define N_TYPES 64
#define E_MAX   500000
#define N_MAX   1000000
#define THREADS 256            // prep/final block size
#define MAIN_THREADS 768       // 24 warps, 1 block/SM (smem-bound)
#define MAIN_GRID 148
#define FILT_WORDS 576         // 24*24
#define FILT_STRIDE 580        // padded: 16B-aligned, spreads bank groups
#define SMEM_BYTES (N_TYPES * FILT_STRIDE * 4)   // 148480 B

__device__ float4 g_u4[N_MAX];    // padded input  [N,4]
__device__ float4 g_acc[N_MAX];   // padded output accumulator [N,4]

// vectorized no-return reduction (PTX ISA 8.1+, sm_90+); 16B-aligned target
__device__ __forceinline__ void red_add_v4(float4* addr, float a, float b, float c)
{
    asm volatile("red.global.add.v4.f32 [%0], {%1, %2, %3, %4};"
                 :: "l"(addr), "f"(a), "f"(b), "f"(c), "f"(0.0f)
                 : "memory");
}

// ---- pass 1: pad U, zero accumulator ----
__global__ __launch_bounds__(THREADS) void k_prep(const float* __restrict__ U, int N)
{
    int i = blockIdx.x * THREADS + threadIdx.x;
    if (i < N) {
        g_u4[i]  = make_float4(U[3 * i + 0], U[3 * i + 1], U[3 * i + 2], 0.f);
        g_acc[i] = make_float4(0.f, 0.f, 0.f, 0.f);
    }
}

// ---- pass 2: persistent main matvec, filters staged in smem ----
__global__ __launch_bounds__(MAIN_THREADS, 1) void k_main(
    const float* __restrict__ filters,  // [64, 24, 24]
    const int*   __restrict__ types,    // [E]
    const int*   __restrict__ nodIdx,   // [E, 8]
    int E)
{
    extern __shared__ float sKe[];      // [64][580] padded

    // cooperative, coalesced filter stage: 147KB once per block
    for (int idx = threadIdx.x; idx < N_TYPES * FILT_WORDS; idx += MAIN_THREADS) {
        const int t = idx / FILT_WORDS;
        const int w = idx - t * FILT_WORDS;
        sKe[t * FILT_STRIDE + w] = filters[idx];
    }
    __syncthreads();

    const int stride = MAIN_GRID * MAIN_THREADS;
    for (int e = blockIdx.x * MAIN_THREADS + threadIdx.x; e < E; e += stride) {
        // coalesced type + connectivity reads (natural element order)
        const int t = types[e] & (N_TYPES - 1);
        const int4 na = __ldg(((const int4*)nodIdx) + 2 * e);
        const int4 nb = __ldg(((const int4*)nodIdx) + 2 * e + 1);
        const int ni[8] = {na.x, na.y, na.z, na.w, nb.x, nb.y, nb.z, nb.w};

        // gather: ONE LDG.128 per node from padded U (L2-resident, 8-deep MLP)
        float ue[24];
#pragma unroll
        for (int k = 0; k < 8; k++) {
            const float4 u = __ldg(&g_u4[ni[k]]);
            ue[3 * k + 0] = u.x;
            ue[3 * k + 1] = u.y;
            ue[3 * k + 2] = u.z;
        }

        const float* Ke = &sKe[t * FILT_STRIDE];

        // fused matvec + scatter: per node, 3 row-dots from smem, one red.v4
#pragma unroll
        for (int k = 0; k < 8; k++) {
            float f0 = 0.f, f1 = 0.f, f2 = 0.f;
            const float4* r0 = (const float4*)(Ke + (3 * k + 0) * 24);
            const float4* r1 = (const float4*)(Ke + (3 * k + 1) * 24);
            const float4* r2 = (const float4*)(Ke + (3 * k + 2) * 24);
#pragma unroll
            for (int j4 = 0; j4 < 6; j4++) {
                const float u0 = ue[4 * j4 + 0], u1 = ue[4 * j4 + 1];
                const float u2 = ue[4 * j4 + 2], u3 = ue[4 * j4 + 3];
                const float4 a = r0[j4];
                f0 += a.x * u0 + a.y * u1 + a.z * u2 + a.w * u3;
                const float4 b = r1[j4];
                f1 += b.x * u0 + b.y * u1 + b.z * u2 + b.w * u3;
                const float4 c = r2[j4];
                f2 += c.x * u0 + c.y * u1 + c.z * u2 + c.w * u3;
            }
            red_add_v4(&g_acc[ni[k]], f0, f1, f2);
        }
    }
}

// ---- pass 3: compact g_acc [N,4] -> out [N,3], streaming stores ----
__global__ __launch_bounds__(THREADS) void k_final(float* __restrict__ out, int N)
{
    const int n = blockIdx.x * THREADS + threadIdx.x;
    if (n >= N) return;
    const float4 s = g_acc[n];
    __stwt(out + 3 * n + 0, s.x);
    __stwt(out + 3 * n + 1, s.y);
    __stwt(out + 3 * n + 2, s.z);
}

extern "C" void kernel_launch(void* const* d_in, const int* in_sizes, int n_in,
                              void* d_out, int out_size)
{
    const float* U       = (const float*)d_in[0];   // N*3 floats
    const float* filters = (const float*)d_in[1];   // 64*24*24 floats
    const int*   types   = (const int*)d_in[2];     // E ints
    const int*   nodIdx  = (const int*)d_in[3];     // E*8 ints

    int E = in_sizes[3] / 8;
    if (E > E_MAX) E = E_MAX;
    int N = in_sizes[0] / 3;
    if (N > N_MAX) N = N_MAX;

    float* out = (float*)d_out;

    // opt-in to >48KB dynamic smem. Unconditional (no static guards — harness
    // rule); idempotent and not a stream op, so capture-safe.
    cudaFuncSetAttribute(k_main, cudaFuncAttributeMaxDynamicSharedMemorySize,
                         SMEM_BYTES);

    const int gridN = (N + THREADS - 1) / THREADS;

    k_prep<<<gridN, THREADS>>>(U, N);
    k_main<<<MAIN_GRID, MAIN_THREADS, SMEM_BYTES>>>(filters, types, nodIdx, E);
    k_final<<<gridN, THREADS>>>(out, N);
}

// round 17
// speedup vs baseline: 1.3989x; 1.3989x over previous
#include <cuda_runtime.h>
#include <cuda_bf16.h>

// FEM H8 stiffness matvec (KU = sum_e scatter(K_type(e) @ gather(U,e))).
//
// v12 = v10 (measured 97.0us) + stream-reduction deltas. v11 smem-filter
// experiment measured 129us (LDS conflicts on random per-lane types) — reverted.
//
//   1) k_prep    : pad U [N,3] -> g_u4 [N,4], zero g_acc [N,4], zero histogram
//   2) k_histo   : per-block smem histogram + per-(block,type) range reservation
//   3) k_scan    : parallel exclusive scan -> g_typeBase
//   4) k_scatter : smem-ranked scatter of permuted connectivity; the 6-bit
//                  type is PACKED into word0 bits[24:30) (nodes < 2^20),
//                  so no separate permType array/stream.
//   5) k_main    : matvec over type-grouped elements:
//                  - connectivity (type embedded) read fully coalesced, __ldcs
//                  - warps type-uniform -> Ke loads are L1 broadcasts
//                  - per-node gather = ONE LDG.128 from padded g_u4
//                  - per-node scatter = ONE red.global.add.v4.f32 into g_acc
//   6) k_final   : compact g_acc [N,4] -> out [N,3], streaming stores

#define N_TYPES 64
#define E_MAX   500000
#define N_MAX   1000000
#define THREADS 256
#define BLOCKS_MAX ((E_MAX + THREADS - 1) / THREADS)
#define TYPE_SHIFT 24
#define NODE_MASK  0x00FFFFFF

__device__ int    g_typeCount[N_TYPES];               // per-type totals
__device__ int    g_typeBase[N_TYPES];                // exclusive scan
__device__ int    g_blockBase[BLOCKS_MAX * N_TYPES];  // per-(block,type) base
__device__ int4   g_nodIdxPerm[2 * E_MAX];            // permuted connectivity, type in word0
__device__ float4 g_u4[N_MAX];                        // padded input  [N,4]
__device__ float4 g_acc[N_MAX];                       // padded output accumulator

// vectorized no-return reduction (PTX ISA 8.1+, sm_90+); 16B-aligned target
__device__ __forceinline__ void red_add_v4(float4* addr, float a, float b, float c)
{
    asm volatile("red.global.add.v4.f32 [%0], {%1, %2, %3, %4};"
                 :: "l"(addr), "f"(a), "f"(b), "f"(c), "f"(0.0f)
                 : "memory");
}

// ---- pass 1: pad U, zero accumulator, zero histogram ----
__global__ __launch_bounds__(THREADS) void k_prep(const float* __restrict__ U, int N)
{
    int i = blockIdx.x * THREADS + threadIdx.x;
    if (i < N) {
        g_u4[i]  = make_float4(U[3 * i + 0], U[3 * i + 1], U[3 * i + 2], 0.f);
        g_acc[i] = make_float4(0.f, 0.f, 0.f, 0.f);
    }
    if (blockIdx.x == 0 && threadIdx.x < N_TYPES) g_typeCount[threadIdx.x] = 0;
}

// ---- pass 2: per-block histogram + range reservation ----
__global__ __launch_bounds__(THREADS) void k_histo(const int* __restrict__ types, int E)
{
    __shared__ int h[N_TYPES];
    const int tid = threadIdx.x;
    if (tid < N_TYPES) h[tid] = 0;
    __syncthreads();
    const int e = blockIdx.x * THREADS + tid;
    if (e < E) atomicAdd(&h[types[e] & (N_TYPES - 1)], 1);
    __syncthreads();
    if (tid < N_TYPES)
        g_blockBase[blockIdx.x * N_TYPES + tid] = atomicAdd(&g_typeCount[tid], h[tid]);
}

// ---- pass 3: parallel exclusive scan over 64 per-type totals ----
__global__ void k_scan()
{
    __shared__ int s[N_TYPES];
    const int tid = threadIdx.x;   // 64 threads
    s[tid] = g_typeCount[tid];
    __syncthreads();
#pragma unroll
    for (int d = 1; d < N_TYPES; d <<= 1) {
        int v = (tid >= d) ? s[tid - d] : 0;
        __syncthreads();
        s[tid] += v;
        __syncthreads();
    }
    g_typeBase[tid] = s[tid] - g_typeCount[tid];   // exclusive
}

// ---- pass 4: smem-ranked scatter of permuted connectivity (type packed) ----
__global__ __launch_bounds__(THREADS) void k_scatter(const int* __restrict__ types,
                                                     const int* __restrict__ nodIdx,
                                                     int E)
{
    __shared__ int h[N_TYPES];
    const int tid = threadIdx.x;
    if (tid < N_TYPES) h[tid] = 0;
    __syncthreads();
    const int e = blockIdx.x * THREADS + tid;
    if (e >= E) return;
    const int t = types[e] & (N_TYPES - 1);
    const int rank = atomicAdd(&h[t], 1);          // cheap smem atomic
    const int pos = g_typeBase[t] + g_blockBase[blockIdx.x * N_TYPES + t] + rank;

    // coalesced read-once stream (__ldcs: evict-first, keep L2 for g_u4/g_acc)
    int4 na = __ldcs(((const int4*)nodIdx) + 2 * e);
    const int4 nb = __ldcs(((const int4*)nodIdx) + 2 * e + 1);
    na.x |= (t << TYPE_SHIFT);                     // pack type into word0
    g_nodIdxPerm[2 * pos + 0] = na;
    g_nodIdxPerm[2 * pos + 1] = nb;
}

// ---- pass 5: main matvec over permuted (type-grouped) elements ----
__global__ __launch_bounds__(THREADS) void k_main(
    const float* __restrict__ filters,  // [T, 24, 24]
    int E)
{
    const int i = blockIdx.x * THREADS + threadIdx.x;
    if (i >= E) return;

    // fully coalesced read-once connectivity stream; type in word0 high bits
    const int4 na = __ldcs(&g_nodIdxPerm[2 * i + 0]);
    const int4 nb = __ldcs(&g_nodIdxPerm[2 * i + 1]);
    const int t = (na.x >> TYPE_SHIFT) & (N_TYPES - 1);
    const int ni[8] = {na.x & NODE_MASK, na.y, na.z, na.w,
                       nb.x, nb.y, nb.z, nb.w};

    // gather: ONE LDG.128 per node from padded U (L2-resident; 8-deep MLP)
    float ue[24];
#pragma unroll
    for (int k = 0; k < 8; k++) {
        const float4 u = __ldg(&g_u4[ni[k]]);
        ue[3 * k + 0] = u.x;
        ue[3 * k + 1] = u.y;
        ue[3 * k + 2] = u.z;
    }

    // warp-uniform type -> every Ke load is an L1 broadcast (1 wavefront)
    const float* Ke = filters + (size_t)t * 576;

    // fused matvec + scatter: per node, its 3 row-dots, then ONE red.v4
#pragma unroll
    for (int k = 0; k < 8; k++) {
        float f0 = 0.f, f1 = 0.f, f2 = 0.f;
        const float4* r0 = (const float4*)(Ke + (3 * k + 0) * 24);
        const float4* r1 = (const float4*)(Ke + (3 * k + 1) * 24);
        const float4* r2 = (const float4*)(Ke + (3 * k + 2) * 24);
#pragma unroll
        for (int j4 = 0; j4 < 6; j4++) {
            const float u0 = ue[4 * j4 + 0], u1 = ue[4 * j4 + 1];
            const float u2 = ue[4 * j4 + 2], u3 = ue[4 * j4 + 3];
            const float4 a = __ldg(r0 + j4);
            f0 += a.x * u0 + a.y * u1 + a.z * u2 + a.w * u3;
            const float4 b = __ldg(r1 + j4);
            f1 += b.x * u0 + b.y * u1 + b.z * u2 + b.w * u3;
            const float4 c = __ldg(r2 + j4);
            f2 += c.x * u0 + c.y * u1 + c.z * u2 + c.w * u3;
        }
        red_add_v4(&g_acc[ni[k]], f0, f1, f2);
    }
}

// ---- pass 6: compact g_acc [N,4] -> out [N,3], streaming stores ----
__global__ __launch_bounds__(THREADS) void k_final(float* __restrict__ out, int N)
{
    const int n = blockIdx.x * THREADS + threadIdx.x;
    if (n >= N) return;
    const float4 s = g_acc[n];
    __stwt(out + 3 * n + 0, s.x);
    __stwt(out + 3 * n + 1, s.y);
    __stwt(out + 3 * n + 2, s.z);
}

extern "C" void kernel_launch(void* const* d_in, const int* in_sizes, int n_in,
                              void* d_out, int out_size)
{
    const float* U       = (const float*)d_in[0];   // N*3 floats
    const float* filters = (const float*)d_in[1];   // T*24*24 floats
    const int*   types   = (const int*)d_in[2];     // E ints
    const int*   nodIdx  = (const int*)d_in[3];     // E*8 ints

    int E = in_sizes[3] / 8;
    if (E > E_MAX) E = E_MAX;
    int N = in_sizes[0] / 3;
    if (N > N_MAX) N = N_MAX;

    float* out = (float*)d_out;

    const int gridE = (E + THREADS - 1) / THREADS;
    const int gridN = (N + THREADS - 1) / THREADS;

    k_prep<<<gridN, THREADS>>>(U, N);
    k_histo<<<gridE, THREADS>>>(types, E);
    k_scan<<<1, N_TYPES>>>();
    k_scatter<<<gridE, THREADS>>>(types, nodIdx, E);
    k_main<<<gridE, THREADS>>>(filters, E);
    k_final<<<gridN, THREADS>>>(out, N);
}